// round 4
// baseline (speedup 1.0000x reference)
#include <cuda_runtime.h>
#include <cuda_fp16.h>
#include <cstdint>

// ---------------------------------------------------------------------------
// Problem constants
// ---------------------------------------------------------------------------
#define BATCH   64
#define LAT     556
#define KDIM    150528          // 3*224*224
#define NV      5023
#define VM      3500
#define D3      15069           // NV*3
#define OUTROWS 7079            // 3500 + 3500 + 68 + 11

// GEMM1 tiling
#define BN      64
#define BK      32
#define NBLK    9               // ceil(556/64)
#define KSPLIT  96
#define KITER   49              // 150528 / (96*32)
#define ASTRIDE 20              // u32 stride for smem tiles (conflict-free frag reads)

// Operand scaling: B (enc_W ~ 0.001) pre-scaled by 64; lo parts scaled by 2048.
#define BSCALE      64.f
#define LSCALE      2048.f
#define INV_LSCALE  (1.f / 2048.f)
#define INV_BSCALE  (1.f / 64.f)

// Scratch (device globals -- no allocation allowed)
__device__ double g_latent_d[BATCH * LAT];
__device__ float  g_vert0[BATCH * D3];
__device__ float  g_stats[BATCH * 64];

// ---------------------------------------------------------------------------
// Helpers
// ---------------------------------------------------------------------------
__device__ __forceinline__ uint32_t pack_h2(float a, float b) {
    __half2 p = __floats2half2_rn(a, b);
    return *reinterpret_cast<uint32_t*>(&p);
}

// scaled hi/lo split: v ~= h + l/LSCALE, h = fp16(v), l = fp16((v-h)*LSCALE)
__device__ __forceinline__ void split_hs(float v, float& h, float& l) {
    float hf = __half2float(__float2half_rn(v));
    h = hf;
    l = (v - hf) * LSCALE;
}

__device__ __forceinline__ void mma16816(float* d,
                                         uint32_t a0, uint32_t a1, uint32_t a2, uint32_t a3,
                                         uint32_t b0, uint32_t b1) {
    asm volatile(
        "mma.sync.aligned.m16n8k16.row.col.f32.f16.f16.f32 "
        "{%0,%1,%2,%3}, {%4,%5,%6,%7}, {%8,%9}, {%0,%1,%2,%3};\n"
        : "+f"(d[0]), "+f"(d[1]), "+f"(d[2]), "+f"(d[3])
        : "r"(a0), "r"(a1), "r"(a2), "r"(a3), "r"(b0), "r"(b1));
}

// ---- double-precision scalar geometry (immune to --use_fast_math) ----------
__device__ void aa2mat_d(double ax, double ay, double az, double R[3][3]) {
    double th = sqrt(ax * ax + ay * ay + az * az);
    double inv = 1.0 / fmax(th, 1e-8);
    double ux = ax * inv, uy = ay * inv, uz = az * inv;
    double s = sin(th), c = cos(th), mc = 1.0 - c;
    double uu = ux * ux + uy * uy + uz * uz;
    R[0][0] = 1.0 + mc * (ux * ux - uu);
    R[0][1] = -s * uz + mc * ux * uy;
    R[0][2] = s * uy + mc * ux * uz;
    R[1][0] = s * uz + mc * ux * uy;
    R[1][1] = 1.0 + mc * (uy * uy - uu);
    R[1][2] = -s * ux + mc * uy * uz;
    R[2][0] = -s * uy + mc * ux * uz;
    R[2][1] = s * ux + mc * uy * uz;
    R[2][2] = 1.0 + mc * (uz * uz - uu);
}

__device__ __forceinline__ void xform_d(const double R[3][3], double sc, const double tv[3],
                                        const double vm[3], const double* v, double* o) {
    double wx = v[0] - vm[0], wy = v[1] - vm[1], wz = v[2] - vm[2];
    o[0] = (wx * R[0][0] + wy * R[1][0] + wz * R[2][0]) * sc + tv[0];
    o[1] = (wx * R[0][1] + wy * R[1][1] + wz * R[2][1]) * sc + tv[1];
    o[2] = (wx * R[0][2] + wy * R[1][2] + wz * R[2][2]) * sc + tv[2];
}

__device__ __forceinline__ void cross3_d(const double* a, const double* b, double* o) {
    o[0] = a[1] * b[2] - a[2] * b[1];
    o[1] = a[2] * b[0] - a[0] * b[2];
    o[2] = a[0] * b[1] - a[1] * b[0];
}
__device__ __forceinline__ double dot3_d(const double* a, const double* b) {
    return a[0] * b[0] + a[1] * b[1] + a[2] * b[2];
}

// fp32 per-vertex transform (stats layout: R 0..8, scale 9, t 10..12, vmean 13..15)
__device__ __forceinline__ void xform_f(const float* st, float vx, float vy, float vz,
                                        float& ox, float& oy, float& oz) {
    float wx = vx - st[13], wy = vy - st[14], wz = vz - st[15];
    float sc = st[9];
    ox = fmaf(fmaf(wz, st[6], fmaf(wy, st[3], wx * st[0])), sc, st[10]);
    oy = fmaf(fmaf(wz, st[7], fmaf(wy, st[4], wx * st[1])), sc, st[11]);
    oz = fmaf(fmaf(wz, st[8], fmaf(wy, st[5], wx * st[2])), sc, st[12]);
}

// ---------------------------------------------------------------------------
// K0: init latent accumulator (double) with bias
// ---------------------------------------------------------------------------
__global__ void init_kernel(const float* __restrict__ enc_b) {
    int i = blockIdx.x * 256 + threadIdx.x;
    if (i < BATCH * LAT) g_latent_d[i] = (double)enc_b[i % LAT];
}

// ---------------------------------------------------------------------------
// K1: latent += x @ W  (scaled fp16 hi/lo 4-MMA split, split-K double atomics)
// grid: (NBLK, KSPLIT), block 256
// ---------------------------------------------------------------------------
__global__ void __launch_bounds__(256) gemm1_kernel(const float* __restrict__ x,
                                                    const float* __restrict__ W) {
    __shared__ uint32_t Ah[64 * ASTRIDE], Al[64 * ASTRIDE];
    __shared__ uint32_t Bh[64 * ASTRIDE], Bl[64 * ASTRIDE];

    const int t = threadIdx.x;
    const int n0 = blockIdx.x * BN;
    const int k0 = blockIdx.y * (KITER * BK);

    const int warp = t >> 5, lane = t & 31;
    const int wm = warp & 3;        // m-tile (16 rows each)
    const int wn = warp >> 2;       // n-half (32 cols each)
    const int g = lane >> 2, tg = lane & 3;

    float acch[4][4];   // h*h
    float accm[4][4];   // h*l + l*h (x LSCALE)
    float accl[4][4];   // l*l       (x LSCALE^2)
#pragma unroll
    for (int i = 0; i < 4; i++)
#pragma unroll
        for (int j = 0; j < 4; j++) { acch[i][j] = 0.f; accm[i][j] = 0.f; accl[i][j] = 0.f; }

    const int xr = t >> 2, xq = t & 3;
    const int wnl = t & 63, wkq = t >> 6;
    const int ng = n0 + wnl;
    const bool wvalid = (ng < LAT);

    for (int it = 0; it < KITER; ++it) {
        const int kk = k0 + it * BK;

        // --- x tile (64 x 32 fp32) -> split -> smem ---
        const float* xp = x + (size_t)xr * KDIM + kk;
        float4 v0 = *(const float4*)(xp + xq * 4);
        float4 v1 = *(const float4*)(xp + 16 + xq * 4);
        {
            float h0, l0, h1, l1, h2, l2, h3, l3;
            split_hs(v0.x, h0, l0); split_hs(v0.y, h1, l1);
            split_hs(v0.z, h2, l2); split_hs(v0.w, h3, l3);
            int base = xr * ASTRIDE + xq * 2;
            Ah[base] = pack_h2(h0, h1); Ah[base + 1] = pack_h2(h2, h3);
            Al[base] = pack_h2(l0, l1); Al[base + 1] = pack_h2(l2, l3);
            split_hs(v1.x, h0, l0); split_hs(v1.y, h1, l1);
            split_hs(v1.z, h2, l2); split_hs(v1.w, h3, l3);
            Ah[base + 8] = pack_h2(h0, h1); Ah[base + 9] = pack_h2(h2, h3);
            Al[base + 8] = pack_h2(l0, l1); Al[base + 9] = pack_h2(l2, l3);
        }

        // --- W tile (32 x 64 fp32) column-wise, pre-scale 64, split ---
        {
            float wv[8];
            if (wvalid) {
                const float* wp = W + (size_t)(kk + wkq * 8) * LAT + ng;
#pragma unroll
                for (int i = 0; i < 8; i++) wv[i] = wp[(size_t)i * LAT] * BSCALE;
            } else {
#pragma unroll
                for (int i = 0; i < 8; i++) wv[i] = 0.f;
            }
            int base = wnl * ASTRIDE + wkq * 4;
#pragma unroll
            for (int p = 0; p < 4; p++) {
                float he, le, ho, lo;
                split_hs(wv[2 * p], he, le);
                split_hs(wv[2 * p + 1], ho, lo);
                Bh[base + p] = pack_h2(he, ho);
                Bl[base + p] = pack_h2(le, lo);
            }
        }

        __syncthreads();

        const int m0 = wm * 16;
#pragma unroll
        for (int s = 0; s < 2; s++) {
            int ka = s * 8 + tg;
            uint32_t ah0 = Ah[(m0 + g) * ASTRIDE + ka];
            uint32_t ah1 = Ah[(m0 + g + 8) * ASTRIDE + ka];
            uint32_t ah2 = Ah[(m0 + g) * ASTRIDE + ka + 4];
            uint32_t ah3 = Ah[(m0 + g + 8) * ASTRIDE + ka + 4];
            uint32_t al0 = Al[(m0 + g) * ASTRIDE + ka];
            uint32_t al1 = Al[(m0 + g + 8) * ASTRIDE + ka];
            uint32_t al2 = Al[(m0 + g) * ASTRIDE + ka + 4];
            uint32_t al3 = Al[(m0 + g + 8) * ASTRIDE + ka + 4];
#pragma unroll
            for (int nt = 0; nt < 4; nt++) {
                int nrow = wn * 32 + nt * 8 + g;
                uint32_t bh0 = Bh[nrow * ASTRIDE + ka];
                uint32_t bh1 = Bh[nrow * ASTRIDE + ka + 4];
                uint32_t bl0 = Bl[nrow * ASTRIDE + ka];
                uint32_t bl1 = Bl[nrow * ASTRIDE + ka + 4];
                mma16816(acch[nt], ah0, ah1, ah2, ah3, bh0, bh1);
                mma16816(accm[nt], ah0, ah1, ah2, ah3, bl0, bl1);
                mma16816(accm[nt], al0, al1, al2, al3, bh0, bh1);
                mma16816(accl[nt], al0, al1, al2, al3, bl0, bl1);
            }
        }
        __syncthreads();
    }

    // --- combine scales, accumulate into latent (double atomics: exact) ---
    const int mr0 = wm * 16 + g;
#pragma unroll
    for (int nt = 0; nt < 4; nt++) {
        int ncol = n0 + wn * 32 + nt * 8 + 2 * tg;
        if (ncol < LAT) {
#pragma unroll
            for (int q = 0; q < 4; q++) {
                float v = (acch[nt][q] + (accm[nt][q] + accl[nt][q] * INV_LSCALE) * INV_LSCALE) * INV_BSCALE;
                int row = (q < 2) ? mr0 : (mr0 + 8);
                int col = ncol + (q & 1);
                atomicAdd(&g_latent_d[row * LAT + col], (double)v);
            }
        }
    }
}

// ---------------------------------------------------------------------------
// K2: vert0 = template + shape_p @ shape_basis  (no split-K, single owner/elem)
// grid: 118 blocks, 128 threads; thread owns one j-column, all 64 batches
// ---------------------------------------------------------------------------
__global__ void __launch_bounds__(128) shape_kernel(const float* __restrict__ basis,
                                                    const float* __restrict__ vtempl) {
    __shared__ float sp[100 * 64];  // [k][b], staged in 4 chunks
    const int t = threadIdx.x;

    int j = blockIdx.x * 128 + t;
    int jc = j < D3 ? j : D3 - 1;

    float accv[64];
#pragma unroll
    for (int b = 0; b < 64; b++) accv[b] = 0.f;

    for (int chunk = 0; chunk < 4; chunk++) {
        const int k0 = chunk * 100;
        for (int i = t; i < 100 * 64; i += 128) {
            int k = i >> 6, bb = i & 63;
            sp[i] = (float)g_latent_d[bb * LAT + k0 + k];
        }
        __syncthreads();

        const float* bp = basis + (size_t)k0 * D3 + jc;
        for (int k = 0; k < 100; k++) {
            float bs = bp[(size_t)k * D3];
            const float4* s4 = (const float4*)(sp + k * 64);
#pragma unroll
            for (int q = 0; q < 16; q++) {
                float4 sv = s4[q];
                accv[4 * q + 0] = fmaf(sv.x, bs, accv[4 * q + 0]);
                accv[4 * q + 1] = fmaf(sv.y, bs, accv[4 * q + 1]);
                accv[4 * q + 2] = fmaf(sv.z, bs, accv[4 * q + 2]);
                accv[4 * q + 3] = fmaf(sv.w, bs, accv[4 * q + 3]);
            }
        }
        __syncthreads();
    }

    if (j < D3) {
        float tmpl = vtempl[j];
#pragma unroll
        for (int b = 0; b < 64; b++)
            g_vert0[(size_t)b * D3 + j] = tmpl + accv[b];
    }
}

// ---------------------------------------------------------------------------
// K3: per-batch reductions + scalar geometry (all scalars in DOUBLE)
// NOTE: eyeball vertex rotations are dead code in the reference (indices
// 3931..5023 are written but never read by the output); only eye-centre means
// matter, and means commute with the affine rigid transform.
// ---------------------------------------------------------------------------
__global__ void stats_kernel(const int* __restrict__ landmarks) {
    const int b = blockIdx.x, t = threadIdx.x;
    __shared__ float red[9][256];

    float s[9];
#pragma unroll
    for (int i = 0; i < 9; i++) s[i] = 0.f;

    const float* vb = g_vert0 + (size_t)b * D3;
    for (int v = t; v < NV; v += 256) {
        float px = vb[v * 3], py = vb[v * 3 + 1], pz = vb[v * 3 + 2];
        s[0] += px; s[1] += py; s[2] += pz;
        if (v >= 3931) {
            if (v < 4477) { s[3] += px; s[4] += py; s[5] += pz; }
            else          { s[6] += px; s[7] += py; s[8] += pz; }
        }
    }
#pragma unroll
    for (int i = 0; i < 9; i++) red[i][t] = s[i];
    __syncthreads();
    for (int o = 128; o > 0; o >>= 1) {
        if (t < o)
#pragma unroll
            for (int i = 0; i < 9; i++) red[i][t] += red[i][t + o];
        __syncthreads();
    }

    if (t == 0) {
        float* st = g_stats + b * 64;
        const double* lat = g_latent_d + b * LAT;

        double vm[3], lm[3], rm[3];
#pragma unroll
        for (int i = 0; i < 3; i++) {
            vm[i] = (double)red[i][0] / (double)NV;
            lm[i] = (double)red[3 + i][0] / 546.0;
            rm[i] = (double)red[6 + i][0] / 546.0;
        }

        double R[3][3];
        aa2mat_d(lat[545], lat[546], lat[547], R);
        double scale = lat[551] + 1.0;
        double tv[3] = {lat[548], lat[549], lat[550]};

        // stats[0..15] (fp32 for the per-vertex kernels)
        st[0] = (float)R[0][0]; st[1] = (float)R[0][1]; st[2] = (float)R[0][2];
        st[3] = (float)R[1][0]; st[4] = (float)R[1][1]; st[5] = (float)R[1][2];
        st[6] = (float)R[2][0]; st[7] = (float)R[2][1]; st[8] = (float)R[2][2];
        st[9] = (float)scale;
        st[10] = (float)tv[0]; st[11] = (float)tv[1]; st[12] = (float)tv[2];
        st[13] = (float)vm[0]; st[14] = (float)vm[1]; st[15] = (float)vm[2];

        double lc[3], rc[3];
        xform_d(R, scale, tv, vm, lm, lc);
        xform_d(R, scale, tv, vm, rm, rc);

        // face centre: raw landmark means, then affine transform (double)
        int i4[4] = {landmarks[19], landmarks[22], landmarks[25], landmarks[28]};
        int i2[2] = {landmarks[14], landmarks[18]};
        double fcr[3];
#pragma unroll
        for (int c = 0; c < 3; c++) {
            double m4 = 0.0, m2 = 0.0;
#pragma unroll
            for (int q = 0; q < 4; q++) m4 += (double)vb[i4[q] * 3 + c];
#pragma unroll
            for (int q = 0; q < 2; q++) m2 += (double)vb[i2[q] * 3 + c];
            fcr[c] = (m4 * 0.25 + m2 * 0.5) * 0.5;
        }
        double fc[3];
        xform_d(R, scale, tv, vm, fcr, fc);

        // gaze vectors: (0,0,-1) @ R_rot = -(row 2)
        double Rl[3][3], Rr[3][3];
        aa2mat_d(lat[552], lat[553], 0.0, Rl);
        aa2mat_d(lat[554], lat[555], 0.0, Rr);
        double lg[3] = {-Rl[2][0], -Rl[2][1], -Rl[2][2]};
        double rg[3] = {-Rr[2][0], -Rr[2][1], -Rr[2][2]};
        double cr[3];
        cross3_d(rg, lg, cr);

        // Solve [lg, -rg, cr] * sol = rc - lc (Cramer, double)
        double c1[3] = {-rg[0], -rg[1], -rg[2]};
        double rhs[3] = {rc[0] - lc[0], rc[1] - lc[1], rc[2] - lc[2]};
        double c1xc2[3], rhsxc2[3];
        cross3_d(c1, cr, c1xc2);
        cross3_d(rhs, cr, rhsxc2);
        double det = dot3_d(lg, c1xc2);
        double inv = 1.0 / det;
        double sol0 = dot3_d(rhs, c1xc2) * inv;
        double sol1 = dot3_d(lg, rhsxc2) * inv;

        double gpl[3], gpr[3], gpm[3];
#pragma unroll
        for (int c = 0; c < 3; c++) {
            gpl[c] = lc[c] + sol0 * lg[c];
            gpr[c] = rc[c] + sol1 * rg[c];
            gpm[c] = 0.5 * (gpl[c] + gpr[c]);
        }
        double dd[3] = {gpl[0] - gpr[0], gpl[1] - gpr[1], gpl[2] - gpr[2]};
        double dist = sqrt(dot3_d(dd, dd));

#pragma unroll
        for (int c = 0; c < 3; c++) {
            st[16 + c] = (float)lc[c];
            st[19 + c] = (float)rc[c];
            st[22 + c] = (float)fc[c];
            st[25 + c] = (float)gpl[c];
            st[28 + c] = (float)gpr[c];
            st[31 + c] = (float)gpm[c];
            st[34 + c] = (float)(lc[c] + lg[c] * 1000.0);
            st[37 + c] = (float)(rc[c] + rg[c] * 1000.0);
            st[40 + c] = (float)lg[c];
            st[43 + c] = (float)rg[c];
        }
        st[46] = (float)dist;
    }
}

// ---------------------------------------------------------------------------
// K4: output assembly (vmk + projection + fl3d + small rows)
// grid: (28, 64), block 128 -- logical rows 0..3578 per batch
// ---------------------------------------------------------------------------
__global__ void out_kernel(const float* __restrict__ cam,
                           const int* __restrict__ mlm,
                           float* __restrict__ out) {
    const int b = blockIdx.y;
    const int r = blockIdx.x * 128 + threadIdx.x;
    const float* st = g_stats + b * 64;
    const float* vb = g_vert0 + (size_t)b * D3;
    float* ob = out + (size_t)b * OUTROWS * 3;

    if (r < 3500) {
        float wx, wy, wz;
        xform_f(st, vb[r * 3], vb[r * 3 + 1], vb[r * 3 + 2], wx, wy, wz);
        ob[r * 3] = wx; ob[r * 3 + 1] = wy; ob[r * 3 + 2] = wz;

        const float* C = cam + b * 12;
        float p0 = fmaf(C[2], wz, fmaf(C[1], wy, fmaf(C[0], wx, C[3])));
        float p1 = fmaf(C[6], wz, fmaf(C[5], wy, fmaf(C[4], wx, C[7])));
        float p2 = fmaf(C[10], wz, fmaf(C[9], wy, fmaf(C[8], wx, C[11])));
        float zs = (p2 >= 0.f ? 1.f : -1.f) * fmaxf(fabsf(p2), 0.001f);
        size_t o2 = (size_t)(3500 + r) * 3;
        ob[o2] = __fdiv_rn(p0, zs);
        ob[o2 + 1] = __fdiv_rn(p1, zs);
        ob[o2 + 2] = p2;
    } else if (r < 3568) {
        int i = r - 3500;
        int vi = mlm[i];
        float wx, wy, wz;
        xform_f(st, vb[vi * 3], vb[vi * 3 + 1], vb[vi * 3 + 2], wx, wy, wz);
        size_t o = (size_t)(7000 + i) * 3;
        ob[o] = wx; ob[o + 1] = wy; ob[o + 2] = wz;
    } else if (r < 3578) {
        int sidx = r - 3568;
        size_t o = (size_t)(7068 + sidx) * 3;
        ob[o] = st[16 + 3 * sidx];
        ob[o + 1] = st[17 + 3 * sidx];
        ob[o + 2] = st[18 + 3 * sidx];
    } else if (r == 3578) {
        float d = st[46];
        size_t o = (size_t)7078 * 3;
        ob[o] = d; ob[o + 1] = d; ob[o + 2] = d;
    }
}

// ---------------------------------------------------------------------------
// Launch
// ---------------------------------------------------------------------------
extern "C" void kernel_launch(void* const* d_in, const int* in_sizes, int n_in,
                              void* d_out, int out_size) {
    const float* x      = (const float*)d_in[0];
    const float* enc_W  = (const float*)d_in[1];
    const float* enc_b  = (const float*)d_in[2];
    const float* vtempl = (const float*)d_in[3];
    const float* basis  = (const float*)d_in[4];
    const float* cam    = (const float*)d_in[5];
    const int* landmarks = (const int*)d_in[6];
    const int* mlm       = (const int*)d_in[7];
    float* out = (float*)d_out;

    init_kernel<<<(BATCH * LAT + 255) / 256, 256>>>(enc_b);
    gemm1_kernel<<<dim3(NBLK, KSPLIT), 256>>>(x, enc_W);
    shape_kernel<<<118, 128>>>(basis, vtempl);
    stats_kernel<<<BATCH, 256>>>(landmarks);
    out_kernel<<<dim3(28, BATCH), 128>>>(cam, mlm, out);
}